// round 12
// baseline (speedup 1.0000x reference)
#include <cuda_runtime.h>
#include <cuda_fp16.h>
#include <cstdint>

// OctonionLinear as dense fp16 mma.sync GEMM, fp32 accumulate.
//   Y[b, n] = sum_kk X[b, kk] * Bop(n, kk) + bias[n]
//   Bop(n=8i+c, kk) = W[i*32768 + kk*8 + c]
// R12: X pre-converted to fp16 (reused 32x -> worth it), W converted INSIDE the
// GEMM (zero reuse -> avoid the 96MB pre-convert round trip). A via 4-stage
// cp.async from Xh; B via LDG.128 fp32 -> pk2 -> STS, reg-pipelined 1 kt ahead.
// Split-K(2), 2 CTAs/SM, atomicAdd epilogue.

#define M_DIM 512
#define N_DIM 4096
#define K_DIM 4096
#define BM 128
#define BN 128
#define BK 32
#define NK (K_DIM / BK)            // 128
#define KSPLIT 2
#define NK_PER (NK / KSPLIT)       // 64
#define THREADS 256
#define STAGES 4

#define A_STRIDE_H 40                          // fp16 per row (80 B, conflict-free)
#define TILE_H (BM * A_STRIDE_H)               // 5120 halves = 10240 B per tile
#define SMEM_BYTES (STAGES * 2 * TILE_H * 2)   // 81920 B

__device__ __align__(16) __half Xh_g[(size_t)M_DIM * K_DIM];  // 4 MB, [b][kk]

// ---------------- X conversion kernel (12 MB traffic, ~2 us) ----------------
#define CONV_XBLOCKS 2048   // 2M floats / 1024 per block

__global__ __launch_bounds__(256)
void oct_convert_x(const float* __restrict__ X)
{
    const size_t gid = (size_t)blockIdx.x * 1024 + (size_t)threadIdx.x * 4;
    float4 v = *(const float4*)(X + gid);
    __half2* dst = (__half2*)(Xh_g + gid);
    dst[0] = __floats2half2_rn(v.x, v.y);
    dst[1] = __floats2half2_rn(v.z, v.w);
}

// ---------------- GEMM kernel ----------------
__device__ __forceinline__ uint32_t smem_u32(const void* p) {
    uint32_t a;
    asm("{ .reg .u64 t; cvta.to.shared.u64 t, %1; cvt.u32.u64 %0, t; }" : "=r"(a) : "l"(p));
    return a;
}
__device__ __forceinline__ uint32_t pk2(float a, float b) {
    __half2 h = __floats2half2_rn(a, b);
    return *(uint32_t*)&h;
}
__device__ __forceinline__ void cp16(uint32_t dst, const void* src) {
    asm volatile("cp.async.cg.shared.global [%0], [%1], 16;" :: "r"(dst), "l"(src));
}
#define CP_COMMIT() asm volatile("cp.async.commit_group;" ::: "memory")
#define CP_WAIT2()  asm volatile("cp.async.wait_group 2;" ::: "memory")
__device__ __forceinline__ void ldm4(uint32_t* r, uint32_t addr) {
    asm volatile("ldmatrix.sync.aligned.m8n8.x4.shared.b16 {%0,%1,%2,%3}, [%4];"
                 : "=r"(r[0]), "=r"(r[1]), "=r"(r[2]), "=r"(r[3]) : "r"(addr));
}
__device__ __forceinline__ void mma16(float* c, const uint32_t* a, const uint32_t* b) {
    asm volatile(
        "mma.sync.aligned.m16n8k16.row.col.f32.f16.f16.f32 "
        "{%0,%1,%2,%3}, {%4,%5,%6,%7}, {%8,%9}, {%0,%1,%2,%3};"
        : "+f"(c[0]), "+f"(c[1]), "+f"(c[2]), "+f"(c[3])
        : "r"(a[0]), "r"(a[1]), "r"(a[2]), "r"(a[3]), "r"(b[0]), "r"(b[1]));
}

__global__ __launch_bounds__(THREADS, 2)
void oct_mma_fp16_hyb(const float* __restrict__ W,
                      const float* __restrict__ Bias,
                      float* __restrict__ Y)
{
    extern __shared__ __half hsm[];
    __half* Asm = hsm;                         // STAGES tiles (A)
    __half* Bsm = hsm + STAGES * TILE_H;       // STAGES tiles (B)
    const uint32_t sAu = smem_u32(Asm);
    const uint32_t sBu = smem_u32(Bsm);

    const int t = threadIdx.x;
    const int w = t >> 5;
    const int l = t & 31;
    const int bm = blockIdx.y * BM;
    const int bn = blockIdx.x * BN;
    const int ks0 = blockIdx.z * NK_PER;
    const int wm = (w & 3) * 32;
    const int wn = (w >> 2) * 64;
    const int wnOct = wn >> 3;

    const int lr = l >> 2;
    const int lc = l & 3;
    const int i0 = bn >> 3;

    // ---- A cp.async mapping: per thread 2 granules of 16B ----
    const int grow0 = t >> 2;              // +64 per r
    const int gc16  = t & 3;               // 16B column within 64B row

    auto issue_cpA = [&](int kt, int s) {
        const uint32_t aBase = sAu + (uint32_t)s * (TILE_H * 2);
        const size_t kc0 = (size_t)kt * BK + gc16 * 8;
        #pragma unroll
        for (int r = 0; r < 2; r++) {
            const int row = grow0 + r * 64;
            cp16(aBase + (uint32_t)row * 80 + (uint32_t)gc16 * 16,
                 Xh_g + (size_t)(bm + row) * K_DIM + kc0);
        }
    };

    // ---- B LDG/STS mapping (fp32 W -> fp16 smem), reg-pipelined ----
    const int bs    = t & 31;             // slot within oct
    const int bkk0  = (bs >> 1) * 2;      // even kk
    const int bch   = bs & 1;             // c-half (c 0-3 or 4-7)
    const int boct0 = t >> 5;             // oct for r=0; +8 for r=1

    float4 pb[4];

    auto ldgB = [&](int kt) {
        #pragma unroll
        for (int r = 0; r < 2; r++) {
            const float* wb = W + (size_t)(i0 + boct0 + r * 8) * 32768
                                + (size_t)kt * 256 + bkk0 * 8 + bch * 4;
            pb[2 * r]     = *(const float4*)(wb);
            pb[2 * r + 1] = *(const float4*)(wb + 8);   // kk0+1, same c-half
        }
    };
    auto stsB = [&](int s) {
        __half* bS = Bsm + s * TILE_H;
        #pragma unroll
        for (int r = 0; r < 2; r++) {
            const float* lo = (const float*)&pb[2 * r];
            const float* hi = (const float*)&pb[2 * r + 1];
            const int nb = (boct0 + r * 8) * 8 + bch * 4;
            #pragma unroll
            for (int c = 0; c < 4; c++)
                *(uint32_t*)(bS + (nb + c) * A_STRIDE_H + bkk0) = pk2(lo[c], hi[c]);
        }
    };

    // ---- ldmatrix lane addresses (bytes from stage base) ----
    const int aRow = wm + (l & 7) + ((l >> 3) & 1) * 8;
    const uint32_t aOff0 = (uint32_t)(aRow * A_STRIDE_H + ((l >> 4) & 1) * 8) * 2;
    const uint32_t aOff1 = aOff0 + 16 * A_STRIDE_H * 2;
    const int bRow = (wnOct + ((l >> 4) & 1)) * 8 + (l & 7);
    const uint32_t bOff0 = (uint32_t)(bRow * A_STRIDE_H + ((l >> 3) & 1) * 8) * 2;

    // ---- acc init: split 0 carries bias, split 1 zero ----
    float acc[2][8][4];
    if (blockIdx.z == 0) {
        #pragma unroll
        for (int j = 0; j < 8; j++) {
            const int n0 = bn + wn + j * 8 + lc * 2;
            const float b0v = Bias[n0];
            const float b1v = Bias[n0 + 1];
            #pragma unroll
            for (int mi = 0; mi < 2; mi++) {
                acc[mi][j][0] = b0v; acc[mi][j][1] = b1v;
                acc[mi][j][2] = b0v; acc[mi][j][3] = b1v;
            }
        }
    } else {
        #pragma unroll
        for (int mi = 0; mi < 2; mi++)
            #pragma unroll
            for (int j = 0; j < 8; j++)
                #pragma unroll
                for (int q = 0; q < 4; q++) acc[mi][j][q] = 0.0f;
    }

    // ---- prologue ----
    ldgB(ks0 + 0);
    stsB(0);
    ldgB(ks0 + 1);                 // regs hold tile 1
    #pragma unroll
    for (int s = 0; s < STAGES - 1; s++) {   // A tiles 0..2 in flight
        issue_cpA(ks0 + s, s);
        CP_COMMIT();
    }
    CP_WAIT2();                    // A stage 0 complete
    __syncthreads();

    for (int kt = 0; kt < NK_PER; kt++) {
        const int s = kt & (STAGES - 1);
        const uint32_t sAst = sAu + (uint32_t)s * (TILE_H * 2);
        const uint32_t sBst = sBu + (uint32_t)s * (TILE_H * 2);

        // refill A slot (kt+3)&3 (last read at iter kt-1, barrier-protected)
        if (kt + STAGES - 1 < NK_PER)
            issue_cpA(ks0 + kt + STAGES - 1, (kt + STAGES - 1) & (STAGES - 1));
        CP_COMMIT();

        #pragma unroll
        for (int kc = 0; kc < 2; kc++) {
            const uint32_t kb = (uint32_t)kc * 32;   // 16 fp16 = 32 B
            uint32_t aF[2][4], bF[8][2];
            ldm4(aF[0], sAst + aOff0 + kb);
            ldm4(aF[1], sAst + aOff1 + kb);
            #pragma unroll
            for (int p = 0; p < 4; p++)
                ldm4(&bF[2 * p][0], sBst + bOff0 + (uint32_t)p * (16 * A_STRIDE_H * 2) + kb);
            #pragma unroll
            for (int mi = 0; mi < 2; mi++)
                #pragma unroll
                for (int j = 0; j < 8; j++)
                    mma16(acc[mi][j], aF[mi], bF[j]);
        }

        // B: store tile kt+1 (in regs) into stage (kt+1)&3; then LDG tile kt+2
        if (kt + 1 < NK_PER) stsB((kt + 1) & (STAGES - 1));
        if (kt + 2 < NK_PER) ldgB(ks0 + kt + 2);

        if (kt + 1 < NK_PER) {
            CP_WAIT2();           // A stage kt+1 complete
            __syncthreads();      // B stage kt+1 visible; read slots freed
        }
    }

    // ---- epilogue: atomicAdd partial sums into zeroed Y ----
    const int r0 = bm + wm + lr;
    #pragma unroll
    for (int mi = 0; mi < 2; mi++) {
        #pragma unroll
        for (int j = 0; j < 8; j++) {
            const int n0 = bn + wn + j * 8 + lc * 2;
            float* y0 = Y + (size_t)(r0 + mi * 16) * N_DIM + n0;
            float* y1 = Y + (size_t)(r0 + mi * 16 + 8) * N_DIM + n0;
            atomicAdd(y0,     acc[mi][j][0]);
            atomicAdd(y0 + 1, acc[mi][j][1]);
            atomicAdd(y1,     acc[mi][j][2]);
            atomicAdd(y1 + 1, acc[mi][j][3]);
        }
    }
}

extern "C" void kernel_launch(void* const* d_in, const int* in_sizes, int n_in,
                              void* d_out, int out_size)
{
    const float* x    = (const float*)d_in[0];  // [512, 4096]
    const float* wt   = (const float*)d_in[1];  // [512, 512, 8, 8]
    const float* bias = (const float*)d_in[2];  // [512, 8]
    float* y          = (float*)d_out;          // [512, 4096]

    cudaMemsetAsync(y, 0, (size_t)M_DIM * N_DIM * sizeof(float));
    oct_convert_x<<<CONV_XBLOCKS, 256>>>(x);

    cudaFuncSetAttribute(oct_mma_fp16_hyb, cudaFuncAttributeMaxDynamicSharedMemorySize, SMEM_BYTES);
    dim3 grid(N_DIM / BN, M_DIM / BM, KSPLIT);  // (32, 4, 2) = 256 CTAs
    oct_mma_fp16_hyb<<<grid, THREADS, SMEM_BYTES>>>(wt, bias, y);
}

// round 13
// speedup vs baseline: 1.4490x; 1.4490x over previous
#include <cuda_runtime.h>
#include <cuda_fp16.h>
#include <cstdint>

// OctonionLinear as dense fp16 mma.sync GEMM, fp32 accumulate.
//   Y[b, n] = sum_kk X[b, kk] * Bop(n, kk) + bias[n]
//   Bop(n=8i+c, kk) = W[i*32768 + kk*8 + c]
// R13: R11 engine (pre-converted fp16 Xh/Wh, full cp.async GEMM) with BK=64:
// 32 iterations (half the barriers), 3-stage pipeline, 2 CTAs/SM, split-K(2),
// atomicAdd epilogue. Y-zeroing folded into the convert kernel.

#define M_DIM 512
#define N_DIM 4096
#define K_DIM 4096
#define BM 128
#define BN 128
#define BK 64
#define NK (K_DIM / BK)            // 64
#define KSPLIT 2
#define NK_PER (NK / KSPLIT)       // 32
#define THREADS 256
#define STAGES 3

#define STRIDE_H 72                            // fp16 per row (144 B, conflict-free)
#define TILE_H (BM * STRIDE_H)                 // 9216 halves = 18432 B per tile
#define SMEM_BYTES (STAGES * 2 * TILE_H * 2)   // 110592 B

__device__ __align__(16) __half Wh_g[(size_t)N_DIM * K_DIM];  // 32 MB, [n][kk]
__device__ __align__(16) __half Xh_g[(size_t)M_DIM * K_DIM];  // 4 MB,  [b][kk]

// ------------- convert + zero kernel -------------
#define CONV_WBLOCKS 8192   // 512 octets x 16 kk-chunks of 256
#define CONV_XBLOCKS 2048   // 2M floats / 1024 per block
#define ZERO_BLOCKS  2048   // 2M floats / 1024 per block

__global__ __launch_bounds__(256)
void oct_convert(const float* __restrict__ W, const float* __restrict__ X,
                 float* __restrict__ Y)
{
    const int t = threadIdx.x;
    const int b = blockIdx.x;
    if (b < CONV_WBLOCKS) {
        const int i = b >> 4;
        const int kk0 = (b & 15) << 8;
        __shared__ __half sm[8][264];          // [c][kk]
        const float4* src = (const float4*)(W + (size_t)i * 32768 + (size_t)kk0 * 8);
        #pragma unroll
        for (int r = 0; r < 2; r++) {
            const int g = t + r * 256;         // float4 id: kk = g>>1, c0 = (g&1)*4
            float4 v = src[g];
            const int kk = g >> 1, c0 = (g & 1) * 4;
            sm[c0 + 0][kk] = __float2half_rn(v.x);
            sm[c0 + 1][kk] = __float2half_rn(v.y);
            sm[c0 + 2][kk] = __float2half_rn(v.z);
            sm[c0 + 3][kk] = __float2half_rn(v.w);
        }
        __syncthreads();
        const int c = t >> 5, j0 = (t & 31) * 8;
        uint4 out = *(const uint4*)&sm[c][j0];
        *(uint4*)(Wh_g + (size_t)(8 * i + c) * K_DIM + kk0 + j0) = out;
    } else if (b < CONV_WBLOCKS + CONV_XBLOCKS) {
        const size_t gid = (size_t)(b - CONV_WBLOCKS) * 1024 + (size_t)t * 4;
        float4 v = *(const float4*)(X + gid);
        __half2* dst = (__half2*)(Xh_g + gid);
        dst[0] = __floats2half2_rn(v.x, v.y);
        dst[1] = __floats2half2_rn(v.z, v.w);
    } else {
        const size_t gid = (size_t)(b - CONV_WBLOCKS - CONV_XBLOCKS) * 1024
                         + (size_t)t * 4;
        *(float4*)(Y + gid) = make_float4(0.f, 0.f, 0.f, 0.f);
    }
}

// ------------- GEMM kernel -------------
__device__ __forceinline__ uint32_t smem_u32(const void* p) {
    uint32_t a;
    asm("{ .reg .u64 t; cvta.to.shared.u64 t, %1; cvt.u32.u64 %0, t; }" : "=r"(a) : "l"(p));
    return a;
}
__device__ __forceinline__ void cp16(uint32_t dst, const void* src) {
    asm volatile("cp.async.cg.shared.global [%0], [%1], 16;" :: "r"(dst), "l"(src));
}
#define CP_COMMIT() asm volatile("cp.async.commit_group;" ::: "memory")
#define CP_WAIT1()  asm volatile("cp.async.wait_group 1;" ::: "memory")
__device__ __forceinline__ void ldm4(uint32_t* r, uint32_t addr) {
    asm volatile("ldmatrix.sync.aligned.m8n8.x4.shared.b16 {%0,%1,%2,%3}, [%4];"
                 : "=r"(r[0]), "=r"(r[1]), "=r"(r[2]), "=r"(r[3]) : "r"(addr));
}
__device__ __forceinline__ void mma16(float* c, const uint32_t* a, const uint32_t* b) {
    asm volatile(
        "mma.sync.aligned.m16n8k16.row.col.f32.f16.f16.f32 "
        "{%0,%1,%2,%3}, {%4,%5,%6,%7}, {%8,%9}, {%0,%1,%2,%3};"
        : "+f"(c[0]), "+f"(c[1]), "+f"(c[2]), "+f"(c[3])
        : "r"(a[0]), "r"(a[1]), "r"(a[2]), "r"(a[3]), "r"(b[0]), "r"(b[1]));
}

__global__ __launch_bounds__(THREADS, 2)
void oct_mma_fp16_bk64(const float* __restrict__ Bias, float* __restrict__ Y)
{
    extern __shared__ __half hsm[];
    __half* Asm = hsm;                         // STAGES tiles (A)
    __half* Bsm = hsm + STAGES * TILE_H;       // STAGES tiles (B)
    const uint32_t sAu = smem_u32(Asm);
    const uint32_t sBu = smem_u32(Bsm);

    const int t = threadIdx.x;
    const int w = t >> 5;
    const int l = t & 31;
    const int bm = blockIdx.y * BM;
    const int bn = blockIdx.x * BN;
    const int ks0 = blockIdx.z * NK_PER;
    const int wm = (w & 3) * 32;
    const int wn = (w >> 2) * 64;
    const int wnOct = wn >> 3;

    const int lr = l >> 2;
    const int lc = l & 3;

    // ---- cp.async mapping: tile = 128 rows x 8 granules(16B); 4 per thread ----
    const int grow = t >> 3;               // row for id=t (+32 per r)
    const int gcol = t & 7;                // 16B granule within 128B row

    auto issue_cp = [&](int kt, int s) {
        const uint32_t aBase = sAu + (uint32_t)s * (TILE_H * 2);
        const uint32_t bBase = sBu + (uint32_t)s * (TILE_H * 2);
        const size_t kc0 = (size_t)kt * BK + gcol * 8;
        #pragma unroll
        for (int r = 0; r < 4; r++) {
            const int row = grow + r * 32;
            const uint32_t doff = (uint32_t)row * (STRIDE_H * 2) + (uint32_t)gcol * 16;
            cp16(aBase + doff, Xh_g + (size_t)(bm + row) * K_DIM + kc0);
            cp16(bBase + doff, Wh_g + (size_t)(bn + row) * K_DIM + kc0);
        }
    };

    // ---- ldmatrix lane addresses (bytes from stage base) ----
    const int aRow = wm + (l & 7) + ((l >> 3) & 1) * 8;
    const uint32_t aOff0 = (uint32_t)(aRow * STRIDE_H + ((l >> 4) & 1) * 8) * 2;
    const uint32_t aOff1 = aOff0 + 16 * STRIDE_H * 2;
    const int bRow = (wnOct + ((l >> 4) & 1)) * 8 + (l & 7);
    const uint32_t bOff0 = (uint32_t)(bRow * STRIDE_H + ((l >> 3) & 1) * 8) * 2;

    // ---- acc init: split 0 carries bias, split 1 zero ----
    float acc[2][8][4];
    if (blockIdx.z == 0) {
        #pragma unroll
        for (int j = 0; j < 8; j++) {
            const int n0 = bn + wn + j * 8 + lc * 2;
            const float b0v = Bias[n0];
            const float b1v = Bias[n0 + 1];
            #pragma unroll
            for (int mi = 0; mi < 2; mi++) {
                acc[mi][j][0] = b0v; acc[mi][j][1] = b1v;
                acc[mi][j][2] = b0v; acc[mi][j][3] = b1v;
            }
        }
    } else {
        #pragma unroll
        for (int mi = 0; mi < 2; mi++)
            #pragma unroll
            for (int j = 0; j < 8; j++)
                #pragma unroll
                for (int q = 0; q < 4; q++) acc[mi][j][q] = 0.0f;
    }

    // ---- prologue: stages 0,1 in flight ----
    issue_cp(ks0 + 0, 0); CP_COMMIT();
    issue_cp(ks0 + 1, 1); CP_COMMIT();
    CP_WAIT1();            // stage 0 complete
    __syncthreads();

    for (int kt = 0; kt < NK_PER; kt++) {
        const int s = kt % STAGES;
        const uint32_t sAst = sAu + (uint32_t)s * (TILE_H * 2);
        const uint32_t sBst = sBu + (uint32_t)s * (TILE_H * 2);

        // refill slot (kt+2)%3 (read finished at iter kt-1, barrier-protected)
        if (kt + 2 < NK_PER) issue_cp(ks0 + kt + 2, (kt + 2) % STAGES);
        CP_COMMIT();       // always commit (possibly empty) for uniform group count

        #pragma unroll
        for (int kc = 0; kc < 4; kc++) {
            const uint32_t kb = (uint32_t)kc * 32;   // 16 fp16 = 32 B
            uint32_t aF[2][4], bF[8][2];
            ldm4(aF[0], sAst + aOff0 + kb);
            ldm4(aF[1], sAst + aOff1 + kb);
            #pragma unroll
            for (int p = 0; p < 4; p++)
                ldm4(&bF[2 * p][0], sBst + bOff0 + (uint32_t)p * (16 * STRIDE_H * 2) + kb);
            #pragma unroll
            for (int mi = 0; mi < 2; mi++)
                #pragma unroll
                for (int j = 0; j < 8; j++)
                    mma16(acc[mi][j], aF[mi], bF[j]);
        }

        if (kt + 1 < NK_PER) {
            CP_WAIT1();           // stage kt+1 complete (latest group may pend)
            __syncthreads();
        }
    }

    // ---- epilogue: atomicAdd partial sums into zeroed Y ----
    const int r0 = bm + wm + lr;
    #pragma unroll
    for (int mi = 0; mi < 2; mi++) {
        #pragma unroll
        for (int j = 0; j < 8; j++) {
            const int n0 = bn + wn + j * 8 + lc * 2;
            float* y0 = Y + (size_t)(r0 + mi * 16) * N_DIM + n0;
            float* y1 = Y + (size_t)(r0 + mi * 16 + 8) * N_DIM + n0;
            atomicAdd(y0,     acc[mi][j][0]);
            atomicAdd(y0 + 1, acc[mi][j][1]);
            atomicAdd(y1,     acc[mi][j][2]);
            atomicAdd(y1 + 1, acc[mi][j][3]);
        }
    }
}

extern "C" void kernel_launch(void* const* d_in, const int* in_sizes, int n_in,
                              void* d_out, int out_size)
{
    const float* x    = (const float*)d_in[0];  // [512, 4096]
    const float* wt   = (const float*)d_in[1];  // [512, 512, 8, 8]
    const float* bias = (const float*)d_in[2];  // [512, 8]
    float* y          = (float*)d_out;          // [512, 4096]

    oct_convert<<<CONV_WBLOCKS + CONV_XBLOCKS + ZERO_BLOCKS, 256>>>(wt, x, y);

    cudaFuncSetAttribute(oct_mma_fp16_bk64, cudaFuncAttributeMaxDynamicSharedMemorySize, SMEM_BYTES);
    dim3 grid(N_DIM / BN, M_DIM / BM, KSPLIT);  // (32, 4, 2) = 256 CTAs
    oct_mma_fp16_bk64<<<grid, THREADS, SMEM_BYTES>>>(bias, y);
}